// round 3
// baseline (speedup 1.0000x reference)
#include <cuda_runtime.h>
#include <math.h>
#include <stdint.h>

#define NDIM 784
#define MDIM 2048
#define BDIM 4096
#define CAP  96
#define PMIT 100
#define IHTIT 50
#define NC4  196   // NDIM/4

// ---------------- device scratch ----------------
__device__ float  g_Wn [(size_t)NDIM * MDIM];   // normalized W (784x2048)
__device__ float  g_WT [(size_t)MDIM * NDIM];   // Wn^T (2048x784)
__device__ float  g_eW [(size_t)NDIM * MDIM];   // eta * Wn (rounded)
__device__ float  g_res[(size_t)BDIM * NDIM];   // residual (4096x784)
__device__ float  g_U  [(size_t)BDIM * MDIM];   // pre-threshold matrix
__device__ float  g_Gd [(size_t)BDIM * MDIM];   // dense Gamma
__device__ float  g_cn [MDIM];
__device__ float  g_x  [MDIM];                  // pm normalized iterate
__device__ float  g_t  [NDIM];                  // x @ Wn^T
__device__ float  g_zv [MDIM];                  // unnormalized next iterate
__device__ int    g_idx[(size_t)BDIM * CAP];    // ascending col indices
__device__ float  g_val[(size_t)BDIM * CAP];
__device__ int    g_cnt[BDIM];
__device__ double g_err2[IHTIT];
__device__ double g_yn2;
__device__ float  g_c;                          // last pm norm
__device__ float  g_eta;

// ---------------- setup ----------------
__global__ void zero_kernel(const float* __restrict__ pm) {
    int t = blockIdx.x * blockDim.x + threadIdx.x;
    if (t < IHTIT) g_err2[t] = 0.0;
    if (t == 0) g_yn2 = 0.0;
    if (t < MDIM) g_x[t] = pm[t];
}

__global__ void colnorm_kernel(const float* __restrict__ W) {
    int j = blockIdx.x * blockDim.x + threadIdx.x;
    if (j >= MDIM) return;
    double s = 0.0;
    for (int i = 0; i < NDIM; i++) { double w = (double)W[(size_t)i * MDIM + j]; s += w * w; }
    g_cn[j] = (float)sqrt(s);
}

__global__ void buildwn_kernel(const float* __restrict__ W) {
    int stride = gridDim.x * blockDim.x;
    for (int e = blockIdx.x * blockDim.x + threadIdx.x; e < NDIM * MDIM; e += stride) {
        int i = e / MDIM, j = e % MDIM;
        float v = __fdiv_rn(W[e], g_cn[j]);
        g_Wn[e] = v;
        g_WT[(size_t)j * NDIM + i] = v;
    }
}

__global__ void ynorm_kernel(const float* __restrict__ Y, int n) {
    __shared__ double red[256];
    int tid = threadIdx.x;
    double s = 0.0;
    int stride = gridDim.x * blockDim.x;
    for (int i = blockIdx.x * blockDim.x + tid; i < n; i += stride) {
        double y = (double)Y[i]; s += y * y;
    }
    red[tid] = s; __syncthreads();
    for (int off = 128; off; off >>= 1) {
        if (tid < off) red[tid] += red[tid + off];
        __syncthreads();
    }
    if (tid == 0) atomicAdd(&g_yn2, red[0]);
}

// ---------------- power method (faithful two-stage) ----------------
// s1: t[i] = fp32( sum_j x[j] * Wn[i,j] )   (double accum; products fp32 inputs)
__global__ __launch_bounds__(256) void pm_s1() {
    int w = threadIdx.x >> 5, lane = threadIdx.x & 31;
    int i = blockIdx.x * 8 + w;
    if (i >= NDIM) return;
    const float* wr = g_Wn + (size_t)i * MDIM;
    double s = 0.0;
    for (int j = lane; j < MDIM; j += 32) s += (double)g_x[j] * (double)wr[j];
    for (int off = 16; off; off >>= 1) s += __shfl_down_sync(0xffffffff, s, off);
    if (lane == 0) g_t[i] = (float)s;
}

// s2: z[j] = fp32( sum_i t[i] * Wn[i,j] ) = sum_i t[i]*WT[j,i]
__global__ __launch_bounds__(256) void pm_s2() {
    int w = threadIdx.x >> 5, lane = threadIdx.x & 31;
    int j = blockIdx.x * 8 + w;
    const float* wr = g_WT + (size_t)j * NDIM;
    double s = 0.0;
    for (int i = lane; i < NDIM; i += 32) s += (double)g_t[i] * (double)wr[i];
    for (int off = 16; off; off >>= 1) s += __shfl_down_sync(0xffffffff, s, off);
    if (lane == 0) g_zv[j] = (float)s;
}

// s3: nm = fp32(||z||); x = z / nm (rounded); g_c = nm
__global__ __launch_bounds__(256) void pm_s3() {
    __shared__ double red[256];
    int tid = threadIdx.x;
    double s = 0.0;
    for (int j = tid; j < MDIM; j += 256) { double z = (double)g_zv[j]; s += z * z; }
    red[tid] = s; __syncthreads();
    for (int off = 128; off; off >>= 1) {
        if (tid < off) red[tid] += red[tid + off];
        __syncthreads();
    }
    __shared__ float nmf;
    if (tid == 0) { nmf = (float)sqrt(red[0]); g_c = nmf; }
    __syncthreads();
    float nm = nmf;
    for (int j = tid; j < MDIM; j += 256) g_x[j] = __fdiv_rn(g_zv[j], nm);
}

__global__ void etaw_kernel() {
    if (blockIdx.x == 0 && threadIdx.x == 0) g_eta = __fdiv_rn(2.f, g_c);
}

__global__ void buildew_kernel() {
    float eta = g_eta;
    int stride = gridDim.x * blockDim.x;
    for (int e = blockIdx.x * blockDim.x + threadIdx.x; e < NDIM * MDIM; e += stride)
        g_eW[e] = __fmul_rn(eta, g_Wn[e]);
}

// ---------------- faithful sequential-k SGEMM (128x128 tile, 8x8/thread) ----------------
// mode 0: U = Y    @ eW            (init; A=Y)
// mode 1: U = Gd - eta*(res @ Wn)  (A=res)
__global__ __launch_bounds__(256) void sgemm_seq(const float* __restrict__ Yin, int mode) {
    const float* A = (mode == 0) ? Yin : g_res;
    const float* B = (mode == 0) ? g_eW : g_Wn;
    const int Kd = NDIM, N = MDIM;

    __shared__ float As[8][128];
    __shared__ float Bs[8][128];
    int tid = threadIdx.x;
    int bx = blockIdx.x, by = blockIdx.y;
    int aRow = tid >> 1, aCol = (tid & 1) << 2;
    int bRow = tid >> 5, bCol = (tid & 31) << 2;
    const float* Ab = A + (size_t)(by * 128) * Kd;
    const float* Bb = B + bx * 128;
    float acc[8][8];
#pragma unroll
    for (int i = 0; i < 8; i++)
#pragma unroll
        for (int j = 0; j < 8; j++) acc[i][j] = 0.f;
    int ty = tid >> 4, tx = tid & 15;

    for (int k0 = 0; k0 < Kd; k0 += 8) {
        float4 av = *(const float4*)(Ab + (size_t)aRow * Kd + k0 + aCol);
        float4 bv = *(const float4*)(Bb + (size_t)(k0 + bRow) * N + bCol);
        As[aCol + 0][aRow] = av.x; As[aCol + 1][aRow] = av.y;
        As[aCol + 2][aRow] = av.z; As[aCol + 3][aRow] = av.w;
        *(float4*)(&Bs[bRow][bCol]) = bv;
        __syncthreads();
#pragma unroll
        for (int kk = 0; kk < 8; kk++) {      // ascending k, single accumulator
            float ar[8], br[8];
            *(float4*)(ar)     = *(const float4*)(&As[kk][ty * 8]);
            *(float4*)(ar + 4) = *(const float4*)(&As[kk][ty * 8 + 4]);
            *(float4*)(br)     = *(const float4*)(&Bs[kk][tx * 8]);
            *(float4*)(br + 4) = *(const float4*)(&Bs[kk][tx * 8 + 4]);
#pragma unroll
            for (int i = 0; i < 8; i++)
#pragma unroll
                for (int j = 0; j < 8; j++)
                    acc[i][j] = __fmaf_rn(ar[i], br[j], acc[i][j]);
        }
        __syncthreads();
    }
    float eta = g_eta;
#pragma unroll
    for (int i = 0; i < 8; i++) {
        size_t ro = (size_t)(by * 128 + ty * 8 + i) * N + bx * 128 + tx * 8;
#pragma unroll
        for (int j = 0; j < 8; j++) {
            float v = acc[i][j];
            if (mode == 1)
                v = __fsub_rn(g_Gd[ro + j], __fmul_rn(eta, v));
            g_U[ro + j] = v;
        }
    }
}

// ---------------- radix select over |u| (65th-largest key) ----------------
__device__ unsigned block_select_key(const float* u, int rank,
                                     unsigned* whist, unsigned* sc) {
    int tid = threadIdx.x, wid = tid >> 5;
    unsigned prefix = 0, mask = 0;
    for (int shift = 24; shift >= 0; shift -= 8) {
        for (int i = tid; i < 8 * 256; i += 256) whist[i] = 0;
        __syncthreads();
        for (int col = tid; col < MDIM; col += 256) {
            unsigned key = __float_as_uint(u[col]) & 0x7FFFFFFFu;
            if ((key & mask) == prefix)
                atomicAdd(&whist[(wid << 8) + ((key >> shift) & 0xFFu)], 1u);
        }
        __syncthreads();
        unsigned tot = 0;
#pragma unroll
        for (int w = 0; w < 8; w++) tot += whist[(w << 8) + tid];
        __syncthreads();
        whist[tid] = tot;
        __syncthreads();
        if (tid == 0) {
            unsigned cum = 0; int b = 255;
            for (; b > 0; b--) {
                unsigned h = whist[b];
                if (cum + h > (unsigned)rank) break;
                cum += h;
            }
            sc[0] = (unsigned)b;
            sc[1] = (unsigned)rank - cum;
        }
        __syncthreads();
        prefix |= sc[0] << shift;
        rank = (int)sc[1];
        mask |= 0xFFu << shift;
        __syncthreads();
    }
    return prefix;
}

// ---------------- select: threshold row of U -> ascending sparse + dense Gd ----------------
__global__ __launch_bounds__(256) void select_kernel(const int* __restrict__ Kp) {
    __shared__ float u[MDIM];
    __shared__ unsigned whist[8 * 256];
    __shared__ unsigned sc[2];
    __shared__ int sa[256], sb[256];
    int row = blockIdx.x, tid = threadIdx.x;
    int cbase = tid * 8;
    const float4* up = (const float4*)(g_U + (size_t)row * MDIM + cbase);
    float4 u0 = up[0], u1 = up[1];
    *(float4*)&u[cbase] = u0;
    *(float4*)&u[cbase + 4] = u1;
    __syncthreads();
    unsigned T = block_select_key(u, *Kp, whist, sc);

    // keep mask over this thread's 8 ascending cols
    float v[8] = {u0.x, u0.y, u0.z, u0.w, u1.x, u1.y, u1.z, u1.w};
    int keep = 0, cntl = 0;
#pragma unroll
    for (int q = 0; q < 8; q++) {
        if ((__float_as_uint(v[q]) & 0x7FFFFFFFu) > T) { keep |= 1 << q; cntl++; }
    }
    // Hillis-Steele inclusive scan over 256 thread counts
    sa[tid] = cntl; __syncthreads();
    int* src = sa; int* dst = sb;
#pragma unroll
    for (int off = 1; off < 256; off <<= 1) {
        int x = src[tid];
        if (tid >= off) x += src[tid - off];
        dst[tid] = x; __syncthreads();
        int* tmp = src; src = dst; dst = tmp;
    }
    int excl = src[tid] - cntl;
    int total = src[255];

    int p = excl;
    float4 gd0, gd1;
    float* g0 = &gd0.x; float* g1 = &gd1.x;
#pragma unroll
    for (int q = 0; q < 8; q++) {
        float* gq = (q < 4) ? &g0[q] : &g1[q - 4];
        if (keep & (1 << q)) {
            g_idx[(size_t)row * CAP + p] = cbase + q;
            g_val[(size_t)row * CAP + p] = v[q];
            *gq = v[q];
            p++;
        } else *gq = 0.f;
    }
    float4* gdp = (float4*)(g_Gd + (size_t)row * MDIM + cbase);
    gdp[0] = gd0; gdp[1] = gd1;
    if (tid == 0) g_cnt[row] = total;
}

// ---------------- residual / X: ascending-index 64-term sums ----------------
// doSub=1: res = Gamma@Wn^T - Y (write g_res), optional err accumulation
// doSub=0: out = Gamma@Wn^T (write outp)
__global__ __launch_bounds__(256) void spout_kernel(const float* __restrict__ Y,
                                                    float* __restrict__ outp,
                                                    int doSub, int errSlot) {
    __shared__ int sidx[CAP];
    __shared__ float sval[CAP];
    __shared__ double red[256];
    int row = blockIdx.x, tid = threadIdx.x;
    int cnt = g_cnt[row];
    if (tid < cnt) {
        sidx[tid] = g_idx[(size_t)row * CAP + tid];
        sval[tid] = g_val[(size_t)row * CAP + tid];
    }
    __syncthreads();
    double lerr = 0.0;
    if (tid < NC4) {
        int c4 = tid;  // float4 col index
        float4 acc = make_float4(0.f, 0.f, 0.f, 0.f);
        for (int s = 0; s < cnt; s++) {    // ascending index order
            float vv = sval[s];
            float4 w = *((const float4*)(g_WT + (size_t)sidx[s] * NDIM) + c4);
            acc.x = __fmaf_rn(vv, w.x, acc.x);
            acc.y = __fmaf_rn(vv, w.y, acc.y);
            acc.z = __fmaf_rn(vv, w.z, acc.z);
            acc.w = __fmaf_rn(vv, w.w, acc.w);
        }
        if (doSub) {
            float4 y = *((const float4*)(Y + (size_t)row * NDIM) + c4);
            acc.x = __fsub_rn(acc.x, y.x);
            acc.y = __fsub_rn(acc.y, y.y);
            acc.z = __fsub_rn(acc.z, y.z);
            acc.w = __fsub_rn(acc.w, y.w);
            lerr = (double)acc.x * acc.x + (double)acc.y * acc.y
                 + (double)acc.z * acc.z + (double)acc.w * acc.w;
        }
        float* op = doSub ? (g_res + (size_t)row * NDIM) : (outp + (size_t)row * NDIM);
        *((float4*)op + c4) = acc;
    }
    if (errSlot >= 0) {
        red[tid] = lerr; __syncthreads();
        for (int off = 128; off; off >>= 1) {
            if (tid < off) red[tid] += red[tid + off];
            __syncthreads();
        }
        if (tid == 0) atomicAdd(&g_err2[errSlot], red[0]);
    }
}

// ---------------- outputs ----------------
__global__ __launch_bounds__(256) void copy_gamma(float* __restrict__ out) {
    size_t stride = (size_t)gridDim.x * blockDim.x;
    size_t n4 = (size_t)BDIM * MDIM / 4;
    const float4* src = (const float4*)g_Gd;
    float4* dst = (float4*)out;
    for (size_t e = blockIdx.x * (size_t)blockDim.x + threadIdx.x; e < n4; e += stride)
        dst[e] = src[e];
}

__global__ void write_err(float* __restrict__ out) {
    int t = threadIdx.x;
    if (t < IHTIT) {
        float rn = sqrtf((float)g_err2[t]);
        float yn = sqrtf((float)g_yn2);
        out[t] = __fdiv_rn(rn, yn);
    }
}

// ---------------- host ----------------
extern "C" void kernel_launch(void* const* d_in, const int* in_sizes, int n_in,
                              void* d_out, int out_size) {
    const float* Y  = (const float*)d_in[0];
    const float* W  = (const float*)d_in[1];
    const float* pm = (const float*)d_in[2];
    const int*   Kp = (const int*)d_in[3];
    float* out = (float*)d_out;
    (void)in_sizes; (void)n_in;

    zero_kernel<<<8, 256>>>(pm);
    colnorm_kernel<<<MDIM / 256, 256>>>(W);
    buildwn_kernel<<<1024, 256>>>(W);
    ynorm_kernel<<<512, 256>>>(Y, BDIM * NDIM);

    for (int it = 0; it < PMIT; it++) {
        pm_s1<<<98, 256>>>();       // 784 outputs, warp each
        pm_s2<<<MDIM / 8, 256>>>();
        pm_s3<<<1, 256>>>();
    }
    etaw_kernel<<<1, 32>>>();
    buildew_kernel<<<1024, 256>>>();

    dim3 gGemm(MDIM / 128, BDIM / 128);   // 16 x 32
    sgemm_seq<<<gGemm, 256>>>(Y, 0);      // U = Y @ (eta*Wn)
    select_kernel<<<BDIM, 256>>>(Kp);     // Gamma_0
    spout_kernel<<<BDIM, 256>>>(Y, nullptr, 1, -1);   // residual_0

    for (int t = 1; t <= IHTIT; t++) {
        sgemm_seq<<<gGemm, 256>>>(Y, 1);                    // U = Gd - eta*(res@Wn)
        select_kernel<<<BDIM, 256>>>(Kp);                   // Gamma_t
        spout_kernel<<<BDIM, 256>>>(Y, nullptr, 1, t - 1);  // residual_t + err_t
    }

    long long GOFF = (long long)BDIM * NDIM;          // 3211264
    long long EOFF = GOFF + (long long)BDIM * MDIM;   // 11599872

    spout_kernel<<<BDIM, 256>>>(Y, out, 0, -1);       // X = Gamma @ Wn^T
    if ((long long)out_size >= EOFF)
        copy_gamma<<<1024, 256>>>(out + GOFF);
    if ((long long)out_size >= EOFF + IHTIT)
        write_err<<<1, 64>>>(out + EOFF);
}

// round 4
// speedup vs baseline: 1.1648x; 1.1648x over previous
#include <cuda_runtime.h>
#include <math.h>
#include <stdint.h>

#define NDIM 784
#define MDIM 2048
#define BDIM 4096
#define CAP  96
#define PMIT 100
#define IHTIT 50
#define NC4  196   // NDIM/4
#define PMB  128   // persistent power-method blocks (<=148 SMs, co-resident)

// ---------------- device scratch ----------------
__device__ float  g_Wn [(size_t)NDIM * MDIM];   // normalized W (784x2048)
__device__ float  g_WT [(size_t)MDIM * NDIM];   // Wn^T (2048x784)
__device__ float  g_eW [(size_t)NDIM * MDIM];   // eta * Wn (rounded)
__device__ float  g_res[(size_t)BDIM * NDIM];   // residual (4096x784)
__device__ float  g_U  [(size_t)BDIM * MDIM];   // pre-threshold matrix
__device__ float  g_Gd [(size_t)BDIM * MDIM];   // dense Gamma
__device__ float  g_cn [MDIM];
__device__ float  g_x  [MDIM];                  // pm normalized iterate
__device__ float  g_t  [NDIM];                  // x @ Wn^T
__device__ float  g_zv [MDIM];                  // unnormalized next iterate
__device__ int    g_idx[(size_t)BDIM * CAP];    // ascending col indices
__device__ float  g_val[(size_t)BDIM * CAP];
__device__ int    g_cnt[BDIM];
__device__ double g_err2[IHTIT];
__device__ double g_yn2;
__device__ float  g_c;                          // last pm norm
__device__ float  g_eta;
__device__ unsigned g_bar;                      // grid barrier counter

// ---------------- setup ----------------
__global__ void zero_kernel(const float* __restrict__ pm) {
    int t = blockIdx.x * blockDim.x + threadIdx.x;
    if (t < IHTIT) g_err2[t] = 0.0;
    if (t == 0) { g_yn2 = 0.0; g_bar = 0u; }
    if (t < MDIM) g_x[t] = pm[t];
}

__global__ void colnorm_kernel(const float* __restrict__ W) {
    int j = blockIdx.x * blockDim.x + threadIdx.x;
    if (j >= MDIM) return;
    double s = 0.0;
    for (int i = 0; i < NDIM; i++) { double w = (double)W[(size_t)i * MDIM + j]; s += w * w; }
    g_cn[j] = (float)sqrt(s);
}

__global__ void buildwn_kernel(const float* __restrict__ W) {
    int stride = gridDim.x * blockDim.x;
    for (int e = blockIdx.x * blockDim.x + threadIdx.x; e < NDIM * MDIM; e += stride) {
        int i = e / MDIM, j = e % MDIM;
        float v = __fdiv_rn(W[e], g_cn[j]);
        g_Wn[e] = v;
        g_WT[(size_t)j * NDIM + i] = v;
    }
}

__global__ void ynorm_kernel(const float* __restrict__ Y, int n) {
    __shared__ double red[256];
    int tid = threadIdx.x;
    double s = 0.0;
    int stride = gridDim.x * blockDim.x;
    for (int i = blockIdx.x * blockDim.x + tid; i < n; i += stride) {
        double y = (double)Y[i]; s += y * y;
    }
    red[tid] = s; __syncthreads();
    for (int off = 128; off; off >>= 1) {
        if (tid < off) red[tid] += red[tid + off];
        __syncthreads();
    }
    if (tid == 0) atomicAdd(&g_yn2, red[0]);
}

// ---------------- persistent power method ----------------
__device__ __forceinline__ void grid_bar(unsigned& target) {
    __syncthreads();
    if (threadIdx.x == 0) {
        __threadfence();
        atomicAdd(&g_bar, 1u);
        while (atomicAdd(&g_bar, 0u) < target) __nanosleep(32);
        __threadfence();
    }
    __syncthreads();
    target += PMB;
}

__global__ __launch_bounds__(256) void pm_persist() {
    __shared__ double red[256];
    __shared__ float nmf_s;
    unsigned target = PMB;
    int tid = threadIdx.x, wid = tid >> 5, lane = tid & 31;
    int gw = blockIdx.x * 8 + wid;   // global warp id 0..1023
    for (int it = 0; it < PMIT; it++) {
        // s1: t[i] = fp32( sum_j x[j]*Wn[i,j] ), double accum, lane-strided
        if (gw < NDIM) {
            const float* wr = g_Wn + (size_t)gw * MDIM;
            double s = 0.0;
            for (int j = lane; j < MDIM; j += 32) s += (double)g_x[j] * (double)wr[j];
            for (int off = 16; off; off >>= 1) s += __shfl_down_sync(0xffffffff, s, off);
            if (lane == 0) g_t[gw] = (float)s;
        }
        grid_bar(target);
        // s2: z[j] = fp32( sum_i t[i]*WT[j,i] )
        for (int r = gw; r < MDIM; r += PMB * 8) {
            const float* wr = g_WT + (size_t)r * NDIM;
            double s = 0.0;
            for (int i = lane; i < NDIM; i += 32) s += (double)g_t[i] * (double)wr[i];
            for (int off = 16; off; off >>= 1) s += __shfl_down_sync(0xffffffff, s, off);
            if (lane == 0) g_zv[r] = (float)s;
        }
        grid_bar(target);
        // s3: block 0 only (bitwise-identical to prior single-block kernel)
        if (blockIdx.x == 0) {
            double s = 0.0;
            for (int j = tid; j < MDIM; j += 256) { double z = (double)g_zv[j]; s += z * z; }
            red[tid] = s; __syncthreads();
            for (int off = 128; off; off >>= 1) {
                if (tid < off) red[tid] += red[tid + off];
                __syncthreads();
            }
            if (tid == 0) { nmf_s = (float)sqrt(red[0]); g_c = nmf_s; }
            __syncthreads();
            float nm = nmf_s;
            for (int j = tid; j < MDIM; j += 256) g_x[j] = __fdiv_rn(g_zv[j], nm);
        }
        grid_bar(target);
    }
    if (blockIdx.x == 0 && tid == 0) g_eta = __fdiv_rn(2.f, g_c);
}

__global__ void buildew_kernel() {
    float eta = g_eta;
    int stride = gridDim.x * blockDim.x;
    for (int e = blockIdx.x * blockDim.x + threadIdx.x; e < NDIM * MDIM; e += stride)
        g_eW[e] = __fmul_rn(eta, g_Wn[e]);
}

// ---------------- pipelined faithful SGEMM (128x128 tile, BK=16, dbl-buffered) ----------------
// Per-output math: ascending-k single-accumulator FMA chain (bitwise == prior rounds).
// mode 0: U = Y @ eW            mode 1: U = Gd - eta*(res @ Wn)
__global__ __launch_bounds__(256, 2) void sgemm_seq(const float* __restrict__ Yin, int mode) {
    const float* __restrict__ A = (mode == 0) ? Yin : g_res;
    const float* __restrict__ B = (mode == 0) ? g_eW : g_Wn;
    const int Kd = NDIM, N = MDIM;

    __shared__ float As[2][16][132];   // [k][m], padded
    __shared__ float Bs[2][16][128];   // [k][n]
    int tid = threadIdx.x;
    int bx = blockIdx.x, by = blockIdx.y;
    int aRow = tid >> 1, aCol = (tid & 1) << 3;    // 128 rows x 16 k via 2 float4/thread
    int bRow = tid >> 4, bCol = (tid & 15) << 3;   // 16 k x 128 n via 2 float4/thread
    int ty = tid >> 4, tx = tid & 15;

    const float* Ap = A + (size_t)(by * 128 + aRow) * Kd + aCol;
    const float* Bp = B + (size_t)bRow * N + bx * 128 + bCol;

    float acc[8][8];
#pragma unroll
    for (int i = 0; i < 8; i++)
#pragma unroll
        for (int j = 0; j < 8; j++) acc[i][j] = 0.f;

    // prefetch tile 0
    float4 a0 = *(const float4*)Ap;
    float4 a1 = *(const float4*)(Ap + 4);
    float4 b0 = *(const float4*)Bp;
    float4 b1 = *(const float4*)(Bp + 4);
    As[0][aCol + 0][aRow] = a0.x; As[0][aCol + 1][aRow] = a0.y;
    As[0][aCol + 2][aRow] = a0.z; As[0][aCol + 3][aRow] = a0.w;
    As[0][aCol + 4][aRow] = a1.x; As[0][aCol + 5][aRow] = a1.y;
    As[0][aCol + 6][aRow] = a1.z; As[0][aCol + 7][aRow] = a1.w;
    *(float4*)&Bs[0][bRow][bCol] = b0;
    *(float4*)&Bs[0][bRow][bCol + 4] = b1;
    __syncthreads();

    const int NSTEP = Kd / 16;   // 49
    int buf = 0;
#pragma unroll 1
    for (int step = 0; step < NSTEP; step++) {
        if (step + 1 < NSTEP) {
            const float* An = Ap + (step + 1) * 16;
            a0 = *(const float4*)An;
            a1 = *(const float4*)(An + 4);
            const float* Bn = Bp + (size_t)(step + 1) * 16 * N;
            b0 = *(const float4*)Bn;
            b1 = *(const float4*)(Bn + 4);
        }
#pragma unroll
        for (int kk = 0; kk < 16; kk++) {
            float ar[8], br[8];
            *(float4*)(ar)     = *(const float4*)&As[buf][kk][ty * 8];
            *(float4*)(ar + 4) = *(const float4*)&As[buf][kk][ty * 8 + 4];
            *(float4*)(br)     = *(const float4*)&Bs[buf][kk][tx * 8];
            *(float4*)(br + 4) = *(const float4*)&Bs[buf][kk][tx * 8 + 4];
#pragma unroll
            for (int i = 0; i < 8; i++)
#pragma unroll
                for (int j = 0; j < 8; j++)
                    acc[i][j] = __fmaf_rn(ar[i], br[j], acc[i][j]);
        }
        if (step + 1 < NSTEP) {
            int nb = buf ^ 1;
            As[nb][aCol + 0][aRow] = a0.x; As[nb][aCol + 1][aRow] = a0.y;
            As[nb][aCol + 2][aRow] = a0.z; As[nb][aCol + 3][aRow] = a0.w;
            As[nb][aCol + 4][aRow] = a1.x; As[nb][aCol + 5][aRow] = a1.y;
            As[nb][aCol + 6][aRow] = a1.z; As[nb][aCol + 7][aRow] = a1.w;
            *(float4*)&Bs[nb][bRow][bCol] = b0;
            *(float4*)&Bs[nb][bRow][bCol + 4] = b1;
            __syncthreads();
            buf = nb;
        }
    }

    float eta = g_eta;
#pragma unroll
    for (int i = 0; i < 8; i++) {
        size_t ro = (size_t)(by * 128 + ty * 8 + i) * N + bx * 128 + tx * 8;
        if (mode == 1) {
            float4 gd0 = *(const float4*)(g_Gd + ro);
            float4 gd1 = *(const float4*)(g_Gd + ro + 4);
            float4 v0, v1;
            v0.x = __fsub_rn(gd0.x, __fmul_rn(eta, acc[i][0]));
            v0.y = __fsub_rn(gd0.y, __fmul_rn(eta, acc[i][1]));
            v0.z = __fsub_rn(gd0.z, __fmul_rn(eta, acc[i][2]));
            v0.w = __fsub_rn(gd0.w, __fmul_rn(eta, acc[i][3]));
            v1.x = __fsub_rn(gd1.x, __fmul_rn(eta, acc[i][4]));
            v1.y = __fsub_rn(gd1.y, __fmul_rn(eta, acc[i][5]));
            v1.z = __fsub_rn(gd1.z, __fmul_rn(eta, acc[i][6]));
            v1.w = __fsub_rn(gd1.w, __fmul_rn(eta, acc[i][7]));
            *(float4*)(g_U + ro)     = v0;
            *(float4*)(g_U + ro + 4) = v1;
        } else {
            *(float4*)(g_U + ro)     = make_float4(acc[i][0], acc[i][1], acc[i][2], acc[i][3]);
            *(float4*)(g_U + ro + 4) = make_float4(acc[i][4], acc[i][5], acc[i][6], acc[i][7]);
        }
    }
}

// ---------------- fused: radix-select + sparse write + residual + err ----------------
__global__ __launch_bounds__(256) void select_spout(const float* __restrict__ Y,
                                                    const int* __restrict__ Kp,
                                                    int errSlot) {
    __shared__ float u[MDIM];
    __shared__ unsigned whist[8 * 256];
    __shared__ int sa[256], sb[256];
    __shared__ unsigned sc[2];
    __shared__ int sidx[CAP];
    __shared__ float sval[CAP];
    __shared__ double red[256];
    int row = blockIdx.x, tid = threadIdx.x, wid = tid >> 5;
    int cbase = tid * 8;
    const float4* up = (const float4*)(g_U + (size_t)row * MDIM + cbase);
    float4 u0 = up[0], u1 = up[1];
    *(float4*)&u[cbase] = u0;
    *(float4*)&u[cbase + 4] = u1;
    __syncthreads();

    // --- radix select: key of the (K+1)-th largest |u| ---
    int rank = *Kp;
    unsigned prefix = 0, mask = 0;
    for (int shift = 24; shift >= 0; shift -= 8) {
        for (int i = tid; i < 8 * 256; i += 256) whist[i] = 0;
        __syncthreads();
        for (int col = tid; col < MDIM; col += 256) {
            unsigned key = __float_as_uint(u[col]) & 0x7FFFFFFFu;
            if ((key & mask) == prefix)
                atomicAdd(&whist[(wid << 8) + ((key >> shift) & 0xFFu)], 1u);
        }
        __syncthreads();
        int tot = 0;
#pragma unroll
        for (int w = 0; w < 8; w++) tot += (int)whist[(w << 8) + tid];
        sa[tid] = tot; __syncthreads();
        int* src = sa; int* dst = sb;
#pragma unroll
        for (int off = 1; off < 256; off <<= 1) {
            int x = src[tid];
            if (tid >= off) x += src[tid - off];
            dst[tid] = x; __syncthreads();
            int* tmp = src; src = dst; dst = tmp;
        }
        int suf = src[255] - src[tid];   // count of elements in buckets > tid
        if (suf <= rank && rank < suf + tot) {
            sc[0] = (unsigned)tid;
            sc[1] = (unsigned)(rank - suf);
        }
        __syncthreads();
        prefix |= sc[0] << shift;
        rank = (int)sc[1];
        mask |= 0xFFu << shift;
        __syncthreads();
    }
    unsigned T = prefix;

    // --- threshold + compact to ascending sparse (smem + global) + dense Gd ---
    float v[8] = {u0.x, u0.y, u0.z, u0.w, u1.x, u1.y, u1.z, u1.w};
    int keep = 0, cntl = 0;
#pragma unroll
    for (int q = 0; q < 8; q++)
        if ((__float_as_uint(v[q]) & 0x7FFFFFFFu) > T) { keep |= 1 << q; cntl++; }
    sa[tid] = cntl; __syncthreads();
    {
        int* src = sa; int* dst = sb;
#pragma unroll
        for (int off = 1; off < 256; off <<= 1) {
            int x = src[tid];
            if (tid >= off) x += src[tid - off];
            dst[tid] = x; __syncthreads();
            int* tmp = src; src = dst; dst = tmp;
        }
        int excl = src[tid] - cntl;
        int total = src[255];
        int p = excl;
        float4 gd0, gd1;
        float* gq0 = &gd0.x; float* gq1 = &gd1.x;
#pragma unroll
        for (int q = 0; q < 8; q++) {
            float* gq = (q < 4) ? &gq0[q] : &gq1[q - 4];
            if (keep & (1 << q)) {
                sidx[p] = cbase + q;
                sval[p] = v[q];
                g_idx[(size_t)row * CAP + p] = cbase + q;
                g_val[(size_t)row * CAP + p] = v[q];
                *gq = v[q];
                p++;
            } else *gq = 0.f;
        }
        float4* gdp = (float4*)(g_Gd + (size_t)row * MDIM + cbase);
        gdp[0] = gd0; gdp[1] = gd1;
        if (tid == 0) g_cnt[row] = total;
        sa[tid] = total;       // stash for post-sync read
    }
    __syncthreads();
    int cnt = sa[255] - 0;  // total kept
    cnt = g_cnt[row];       // (same value, already visible after sync)

    // --- residual: res = Gamma@Wn^T - Y (ascending-index 64-term sums) ---
    double lerr = 0.0;
    if (tid < NC4) {
        float4 acc = make_float4(0.f, 0.f, 0.f, 0.f);
        for (int s = 0; s < cnt; s++) {
            float vv = sval[s];
            float4 w = *((const float4*)(g_WT + (size_t)sidx[s] * NDIM) + tid);
            acc.x = __fmaf_rn(vv, w.x, acc.x);
            acc.y = __fmaf_rn(vv, w.y, acc.y);
            acc.z = __fmaf_rn(vv, w.z, acc.z);
            acc.w = __fmaf_rn(vv, w.w, acc.w);
        }
        float4 y = *((const float4*)(Y + (size_t)row * NDIM) + tid);
        acc.x = __fsub_rn(acc.x, y.x);
        acc.y = __fsub_rn(acc.y, y.y);
        acc.z = __fsub_rn(acc.z, y.z);
        acc.w = __fsub_rn(acc.w, y.w);
        lerr = (double)acc.x * acc.x + (double)acc.y * acc.y
             + (double)acc.z * acc.z + (double)acc.w * acc.w;
        *((float4*)(g_res + (size_t)row * NDIM) + tid) = acc;
    }
    if (errSlot >= 0) {
        red[tid] = lerr; __syncthreads();
        for (int off = 128; off; off >>= 1) {
            if (tid < off) red[tid] += red[tid + off];
            __syncthreads();
        }
        if (tid == 0) atomicAdd(&g_err2[errSlot], red[0]);
    }
}

// ---------------- outputs ----------------
__global__ __launch_bounds__(256) void write_x(float* __restrict__ out) {
    __shared__ int sidx[CAP];
    __shared__ float sval[CAP];
    int row = blockIdx.x, tid = threadIdx.x;
    int cnt = g_cnt[row];
    if (tid < cnt) {
        sidx[tid] = g_idx[(size_t)row * CAP + tid];
        sval[tid] = g_val[(size_t)row * CAP + tid];
    }
    __syncthreads();
    if (tid < NC4) {
        float4 acc = make_float4(0.f, 0.f, 0.f, 0.f);
        for (int s = 0; s < cnt; s++) {
            float vv = sval[s];
            float4 w = *((const float4*)(g_WT + (size_t)sidx[s] * NDIM) + tid);
            acc.x = __fmaf_rn(vv, w.x, acc.x);
            acc.y = __fmaf_rn(vv, w.y, acc.y);
            acc.z = __fmaf_rn(vv, w.z, acc.z);
            acc.w = __fmaf_rn(vv, w.w, acc.w);
        }
        *((float4*)(out + (size_t)row * NDIM) + tid) = acc;
    }
}

__global__ __launch_bounds__(256) void copy_gamma(float* __restrict__ out) {
    size_t stride = (size_t)gridDim.x * blockDim.x;
    size_t n4 = (size_t)BDIM * MDIM / 4;
    const float4* src = (const float4*)g_Gd;
    float4* dst = (float4*)out;
    for (size_t e = blockIdx.x * (size_t)blockDim.x + threadIdx.x; e < n4; e += stride)
        dst[e] = src[e];
}

__global__ void write_err(float* __restrict__ out) {
    int t = threadIdx.x;
    if (t < IHTIT) {
        float rn = sqrtf((float)g_err2[t]);
        float yn = sqrtf((float)g_yn2);
        out[t] = __fdiv_rn(rn, yn);
    }
}

// ---------------- host ----------------
extern "C" void kernel_launch(void* const* d_in, const int* in_sizes, int n_in,
                              void* d_out, int out_size) {
    const float* Y  = (const float*)d_in[0];
    const float* W  = (const float*)d_in[1];
    const float* pm = (const float*)d_in[2];
    const int*   Kp = (const int*)d_in[3];
    float* out = (float*)d_out;
    (void)in_sizes; (void)n_in;

    zero_kernel<<<8, 256>>>(pm);
    colnorm_kernel<<<MDIM / 256, 256>>>(W);
    buildwn_kernel<<<1024, 256>>>(W);
    ynorm_kernel<<<512, 256>>>(Y, BDIM * NDIM);

    pm_persist<<<PMB, 256>>>();
    buildew_kernel<<<1024, 256>>>();

    dim3 gGemm(MDIM / 128, BDIM / 128);   // 16 x 32
    sgemm_seq<<<gGemm, 256>>>(Y, 0);            // U = Y @ (eta*Wn)
    select_spout<<<BDIM, 256>>>(Y, Kp, -1);     // Gamma_0 + residual_0

    for (int t = 1; t <= IHTIT; t++) {
        sgemm_seq<<<gGemm, 256>>>(Y, 1);            // U = Gd - eta*(res@Wn)
        select_spout<<<BDIM, 256>>>(Y, Kp, t - 1);  // Gamma_t + residual_t + err
    }

    long long GOFF = (long long)BDIM * NDIM;          // 3211264
    long long EOFF = GOFF + (long long)BDIM * MDIM;   // 11599872

    write_x<<<BDIM, 256>>>(out);
    if ((long long)out_size >= EOFF)
        copy_gamma<<<1024, 256>>>(out + GOFF);
    if ((long long)out_size >= EOFF + IHTIT)
        write_err<<<1, 64>>>(out + EOFF);
}

// round 5
// speedup vs baseline: 1.2695x; 1.0899x over previous
#include <cuda_runtime.h>
#include <math.h>
#include <stdint.h>

#define NDIM 784
#define MDIM 2048
#define BDIM 4096
#define CAP  96
#define PMIT 100
#define IHTIT 50
#define NC4  196   // NDIM/4
#define PMB  128   // persistent power-method blocks

// ---------------- f32x2 packed helpers (per-component IEEE rn; chains preserved) ----
__device__ __forceinline__ unsigned long long pack_dup(float x) {
    unsigned long long r;
    asm("mov.b64 %0, {%1, %1};" : "=l"(r) : "f"(x));
    return r;
}
__device__ __forceinline__ unsigned long long pack2(float x, float y) {
    unsigned long long r;
    asm("mov.b64 %0, {%1, %2};" : "=l"(r) : "f"(x), "f"(y));
    return r;
}
__device__ __forceinline__ void ffma2(unsigned long long& d, unsigned long long a,
                                      unsigned long long b) {
    asm("fma.rn.f32x2 %0, %1, %2, %0;" : "+l"(d) : "l"(a), "l"(b));
}
__device__ __forceinline__ float2 unpack2(unsigned long long v) {
    float2 f;
    asm("mov.b64 {%0, %1}, %2;" : "=f"(f.x), "=f"(f.y) : "l"(v));
    return f;
}

// ---------------- device scratch ----------------
__device__ float  g_Wn [(size_t)NDIM * MDIM];
__device__ float  g_WT [(size_t)MDIM * NDIM];
__device__ float  g_eW [(size_t)NDIM * MDIM];
__device__ float  g_res[(size_t)BDIM * NDIM];
__device__ float  g_U  [(size_t)BDIM * MDIM];
__device__ float  g_Gd [(size_t)BDIM * MDIM];
__device__ float  g_cn [MDIM];
__device__ float  g_x  [MDIM];
__device__ float  g_t  [NDIM];
__device__ float  g_zv [MDIM];
__device__ int    g_idx[(size_t)BDIM * CAP];
__device__ float  g_val[(size_t)BDIM * CAP];
__device__ int    g_cnt[BDIM];
__device__ double g_err2[IHTIT];
__device__ double g_yn2;
__device__ float  g_c;
__device__ float  g_eta;
__device__ unsigned g_bar;

// ---------------- setup ----------------
__global__ void zero_kernel(const float* __restrict__ pm) {
    int t = blockIdx.x * blockDim.x + threadIdx.x;
    if (t < IHTIT) g_err2[t] = 0.0;
    if (t == 0) { g_yn2 = 0.0; g_bar = 0u; }
    if (t < MDIM) g_x[t] = pm[t];
}

__global__ void colnorm_kernel(const float* __restrict__ W) {
    int j = blockIdx.x * blockDim.x + threadIdx.x;
    if (j >= MDIM) return;
    double s = 0.0;
    for (int i = 0; i < NDIM; i++) { double w = (double)W[(size_t)i * MDIM + j]; s += w * w; }
    g_cn[j] = (float)sqrt(s);
}

__global__ void buildwn_kernel(const float* __restrict__ W) {
    int stride = gridDim.x * blockDim.x;
    for (int e = blockIdx.x * blockDim.x + threadIdx.x; e < NDIM * MDIM; e += stride) {
        int i = e / MDIM, j = e % MDIM;
        float v = __fdiv_rn(W[e], g_cn[j]);
        g_Wn[e] = v;
        g_WT[(size_t)j * NDIM + i] = v;
    }
}

__global__ void ynorm_kernel(const float* __restrict__ Y, int n) {
    __shared__ double red[256];
    int tid = threadIdx.x;
    double s = 0.0;
    int stride = gridDim.x * blockDim.x;
    for (int i = blockIdx.x * blockDim.x + tid; i < n; i += stride) {
        double y = (double)Y[i]; s += y * y;
    }
    red[tid] = s; __syncthreads();
    for (int off = 128; off; off >>= 1) {
        if (tid < off) red[tid] += red[tid + off];
        __syncthreads();
    }
    if (tid == 0) atomicAdd(&g_yn2, red[0]);
}

// ---------------- persistent power method ----------------
__device__ __forceinline__ void grid_bar(unsigned& target) {
    __syncthreads();
    if (threadIdx.x == 0) {
        __threadfence();
        atomicAdd(&g_bar, 1u);
        while (atomicAdd(&g_bar, 0u) < target) __nanosleep(32);
        __threadfence();
    }
    __syncthreads();
    target += PMB;
}

__global__ __launch_bounds__(256) void pm_persist() {
    __shared__ double red[256];
    __shared__ float nmf_s;
    unsigned target = PMB;
    int tid = threadIdx.x, wid = tid >> 5, lane = tid & 31;
    int gw = blockIdx.x * 8 + wid;
    for (int it = 0; it < PMIT; it++) {
        if (gw < NDIM) {
            const float* wr = g_Wn + (size_t)gw * MDIM;
            double s = 0.0;
            for (int j = lane; j < MDIM; j += 32) s += (double)g_x[j] * (double)wr[j];
            for (int off = 16; off; off >>= 1) s += __shfl_down_sync(0xffffffff, s, off);
            if (lane == 0) g_t[gw] = (float)s;
        }
        grid_bar(target);
        for (int r = gw; r < MDIM; r += PMB * 8) {
            const float* wr = g_WT + (size_t)r * NDIM;
            double s = 0.0;
            for (int i = lane; i < NDIM; i += 32) s += (double)g_t[i] * (double)wr[i];
            for (int off = 16; off; off >>= 1) s += __shfl_down_sync(0xffffffff, s, off);
            if (lane == 0) g_zv[r] = (float)s;
        }
        grid_bar(target);
        if (blockIdx.x == 0) {
            double s = 0.0;
            for (int j = tid; j < MDIM; j += 256) { double z = (double)g_zv[j]; s += z * z; }
            red[tid] = s; __syncthreads();
            for (int off = 128; off; off >>= 1) {
                if (tid < off) red[tid] += red[tid + off];
                __syncthreads();
            }
            if (tid == 0) { nmf_s = (float)sqrt(red[0]); g_c = nmf_s; }
            __syncthreads();
            float nm = nmf_s;
            for (int j = tid; j < MDIM; j += 256) g_x[j] = __fdiv_rn(g_zv[j], nm);
        }
        grid_bar(target);
    }
    if (blockIdx.x == 0 && tid == 0) g_eta = __fdiv_rn(2.f, g_c);
}

__global__ void buildew_kernel() {
    float eta = g_eta;
    int stride = gridDim.x * blockDim.x;
    for (int e = blockIdx.x * blockDim.x + threadIdx.x; e < NDIM * MDIM; e += stride)
        g_eW[e] = __fmul_rn(eta, g_Wn[e]);
}

// ---------------- pipelined faithful SGEMM with packed FFMA2 ----------------
// Per-output math: ascending-k single-accumulator rn-FMA chain (bitwise preserved;
// f32x2 pairs two DIFFERENT outputs per instruction).
// mode 0: U = Y @ eW            mode 1: U = Gd - eta*(res @ Wn)
__global__ __launch_bounds__(256, 2) void sgemm_seq(const float* __restrict__ Yin, int mode) {
    const float* __restrict__ A = (mode == 0) ? Yin : g_res;
    const float* __restrict__ B = (mode == 0) ? g_eW : g_Wn;
    const int Kd = NDIM, N = MDIM;

    __shared__ float As[2][16][132];
    __shared__ float Bs[2][16][128];
    int tid = threadIdx.x;
    int bx = blockIdx.x, by = blockIdx.y;
    int aRow = tid >> 1, aCol = (tid & 1) << 3;
    int bRow = tid >> 4, bCol = (tid & 15) << 3;
    int ty = tid >> 4, tx = tid & 15;

    const float* Ap = A + (size_t)(by * 128 + aRow) * Kd + aCol;
    const float* Bp = B + (size_t)bRow * N + bx * 128 + bCol;

    unsigned long long acc2[8][4];
#pragma unroll
    for (int i = 0; i < 8; i++)
#pragma unroll
        for (int j = 0; j < 4; j++) acc2[i][j] = 0ull;

    float4 a0 = *(const float4*)Ap;
    float4 a1 = *(const float4*)(Ap + 4);
    float4 b0 = *(const float4*)Bp;
    float4 b1 = *(const float4*)(Bp + 4);
    As[0][aCol + 0][aRow] = a0.x; As[0][aCol + 1][aRow] = a0.y;
    As[0][aCol + 2][aRow] = a0.z; As[0][aCol + 3][aRow] = a0.w;
    As[0][aCol + 4][aRow] = a1.x; As[0][aCol + 5][aRow] = a1.y;
    As[0][aCol + 6][aRow] = a1.z; As[0][aCol + 7][aRow] = a1.w;
    *(float4*)&Bs[0][bRow][bCol] = b0;
    *(float4*)&Bs[0][bRow][bCol + 4] = b1;
    __syncthreads();

    const int NSTEP = Kd / 16;   // 49
    int buf = 0;
#pragma unroll 1
    for (int step = 0; step < NSTEP; step++) {
        if (step + 1 < NSTEP) {
            const float* An = Ap + (step + 1) * 16;
            a0 = *(const float4*)An;
            a1 = *(const float4*)(An + 4);
            const float* Bn = Bp + (size_t)(step + 1) * 16 * N;
            b0 = *(const float4*)Bn;
            b1 = *(const float4*)(Bn + 4);
        }
#pragma unroll
        for (int kk = 0; kk < 16; kk++) {
            float ar[8], br[8];
            *(float4*)(ar)     = *(const float4*)&As[buf][kk][ty * 8];
            *(float4*)(ar + 4) = *(const float4*)&As[buf][kk][ty * 8 + 4];
            *(float4*)(br)     = *(const float4*)&Bs[buf][kk][tx * 8];
            *(float4*)(br + 4) = *(const float4*)&Bs[buf][kk][tx * 8 + 4];
            unsigned long long br2[4];
            br2[0] = pack2(br[0], br[1]); br2[1] = pack2(br[2], br[3]);
            br2[2] = pack2(br[4], br[5]); br2[3] = pack2(br[6], br[7]);
#pragma unroll
            for (int i = 0; i < 8; i++) {
                unsigned long long aa = pack_dup(ar[i]);
                ffma2(acc2[i][0], aa, br2[0]);
                ffma2(acc2[i][1], aa, br2[1]);
                ffma2(acc2[i][2], aa, br2[2]);
                ffma2(acc2[i][3], aa, br2[3]);
            }
        }
        if (step + 1 < NSTEP) {
            int nb = buf ^ 1;
            As[nb][aCol + 0][aRow] = a0.x; As[nb][aCol + 1][aRow] = a0.y;
            As[nb][aCol + 2][aRow] = a0.z; As[nb][aCol + 3][aRow] = a0.w;
            As[nb][aCol + 4][aRow] = a1.x; As[nb][aCol + 5][aRow] = a1.y;
            As[nb][aCol + 6][aRow] = a1.z; As[nb][aCol + 7][aRow] = a1.w;
            *(float4*)&Bs[nb][bRow][bCol] = b0;
            *(float4*)&Bs[nb][bRow][bCol + 4] = b1;
            __syncthreads();
            buf = nb;
        }
    }

    float eta = g_eta;
#pragma unroll
    for (int i = 0; i < 8; i++) {
        size_t ro = (size_t)(by * 128 + ty * 8 + i) * N + bx * 128 + tx * 8;
        float2 c0 = unpack2(acc2[i][0]), c1 = unpack2(acc2[i][1]);
        float2 c2 = unpack2(acc2[i][2]), c3 = unpack2(acc2[i][3]);
        if (mode == 1) {
            float4 gd0 = *(const float4*)(g_Gd + ro);
            float4 gd1 = *(const float4*)(g_Gd + ro + 4);
            float4 v0, v1;
            v0.x = __fsub_rn(gd0.x, __fmul_rn(eta, c0.x));
            v0.y = __fsub_rn(gd0.y, __fmul_rn(eta, c0.y));
            v0.z = __fsub_rn(gd0.z, __fmul_rn(eta, c1.x));
            v0.w = __fsub_rn(gd0.w, __fmul_rn(eta, c1.y));
            v1.x = __fsub_rn(gd1.x, __fmul_rn(eta, c2.x));
            v1.y = __fsub_rn(gd1.y, __fmul_rn(eta, c2.y));
            v1.z = __fsub_rn(gd1.z, __fmul_rn(eta, c3.x));
            v1.w = __fsub_rn(gd1.w, __fmul_rn(eta, c3.y));
            *(float4*)(g_U + ro)     = v0;
            *(float4*)(g_U + ro + 4) = v1;
        } else {
            *(float4*)(g_U + ro)     = make_float4(c0.x, c0.y, c1.x, c1.y);
            *(float4*)(g_U + ro + 4) = make_float4(c2.x, c2.y, c3.x, c3.y);
        }
    }
}

// ---------------- shuffle-based inclusive scan over 256 values ----------------
// returns inclusive scan of v; *totalp = grand total. Uses ws[8] smem. 2 barriers.
__device__ __forceinline__ int block_scan256(int v, int tid, int* ws, int* totalp) {
    int lane = tid & 31, wid = tid >> 5;
    int x = v;
#pragma unroll
    for (int off = 1; off < 32; off <<= 1) {
        int n = __shfl_up_sync(0xffffffff, x, off);
        if (lane >= off) x += n;
    }
    if (lane == 31) ws[wid] = x;
    __syncthreads();
    if (wid == 0) {
        int w = (lane < 8) ? ws[lane] : 0;
#pragma unroll
        for (int off = 1; off < 8; off <<= 1) {
            int n = __shfl_up_sync(0xffffffff, w, off);
            if (lane >= off) w += n;
        }
        if (lane < 8) ws[lane] = w;
    }
    __syncthreads();
    if (wid > 0) x += ws[wid - 1];
    *totalp = ws[7];
    return x;
}

// ---------------- fused: radix-select + sparse write + residual + err ----------------
__global__ __launch_bounds__(256) void select_spout(const float* __restrict__ Y,
                                                    const int* __restrict__ Kp,
                                                    int errSlot) {
    __shared__ float u[MDIM];
    __shared__ unsigned whist[8 * 256];
    __shared__ int ws[8];
    __shared__ unsigned sc[2];
    __shared__ int sidx[CAP];
    __shared__ float sval[CAP];
    __shared__ int scnt_s;
    __shared__ double red[256];
    int row = blockIdx.x, tid = threadIdx.x, wid = tid >> 5;
    int cbase = tid * 8;
    const float4* up = (const float4*)(g_U + (size_t)row * MDIM + cbase);
    float4 u0 = up[0], u1 = up[1];
    *(float4*)&u[cbase] = u0;
    *(float4*)&u[cbase + 4] = u1;
    __syncthreads();

    // --- radix select: key of the (K+1)-th largest |u| ---
    int rank = *Kp;
    unsigned prefix = 0, mask = 0;
    for (int shift = 24; shift >= 0; shift -= 8) {
        for (int i = tid; i < 8 * 256; i += 256) whist[i] = 0;
        __syncthreads();
        for (int col = tid; col < MDIM; col += 256) {
            unsigned key = __float_as_uint(u[col]) & 0x7FFFFFFFu;
            if ((key & mask) == prefix)
                atomicAdd(&whist[(wid << 8) + ((key >> shift) & 0xFFu)], 1u);
        }
        __syncthreads();
        int tot = 0;
#pragma unroll
        for (int w = 0; w < 8; w++) tot += (int)whist[(w << 8) + tid];
        int totalAll;
        int incl = block_scan256(tot, tid, ws, &totalAll);
        int suf = totalAll - incl;   // elements in buckets > tid
        if (suf <= rank && rank < suf + tot) {
            sc[0] = (unsigned)tid;
            sc[1] = (unsigned)(rank - suf);
        }
        __syncthreads();
        prefix |= sc[0] << shift;
        rank = (int)sc[1];
        mask |= 0xFFu << shift;
        __syncthreads();
    }
    unsigned T = prefix;

    // --- threshold + compact to ascending sparse + dense Gd ---
    float v[8] = {u0.x, u0.y, u0.z, u0.w, u1.x, u1.y, u1.z, u1.w};
    int keep = 0, cntl = 0;
#pragma unroll
    for (int q = 0; q < 8; q++)
        if ((__float_as_uint(v[q]) & 0x7FFFFFFFu) > T) { keep |= 1 << q; cntl++; }
    int totalKeep;
    int incl = block_scan256(cntl, tid, ws, &totalKeep);
    int p = incl - cntl;
    float4 gd0, gd1;
    float* gq0 = &gd0.x; float* gq1 = &gd1.x;
#pragma unroll
    for (int q = 0; q < 8; q++) {
        float* gq = (q < 4) ? &gq0[q] : &gq1[q - 4];
        if (keep & (1 << q)) {
            sidx[p] = cbase + q;
            sval[p] = v[q];
            g_idx[(size_t)row * CAP + p] = cbase + q;
            g_val[(size_t)row * CAP + p] = v[q];
            *gq = v[q];
            p++;
        } else *gq = 0.f;
    }
    float4* gdp = (float4*)(g_Gd + (size_t)row * MDIM + cbase);
    gdp[0] = gd0; gdp[1] = gd1;
    if (tid == 0) { g_cnt[row] = totalKeep; scnt_s = totalKeep; }
    __syncthreads();
    int cnt = scnt_s;

    // --- residual: res = Gamma@Wn^T - Y (ascending-index sums, packed FFMA2) ---
    double lerr = 0.0;
    if (tid < NC4) {
        unsigned long long acc2[2] = {0ull, 0ull};
        for (int s = 0; s < cnt; s++) {
            float vv = sval[s];
            unsigned long long vd = pack_dup(vv);
            float4 w = *((const float4*)(g_WT + (size_t)sidx[s] * NDIM) + tid);
            ffma2(acc2[0], vd, pack2(w.x, w.y));
            ffma2(acc2[1], vd, pack2(w.z, w.w));
        }
        float2 r0 = unpack2(acc2[0]), r1 = unpack2(acc2[1]);
        float4 y = *((const float4*)(Y + (size_t)row * NDIM) + tid);
        float4 acc;
        acc.x = __fsub_rn(r0.x, y.x);
        acc.y = __fsub_rn(r0.y, y.y);
        acc.z = __fsub_rn(r1.x, y.z);
        acc.w = __fsub_rn(r1.y, y.w);
        lerr = (double)acc.x * acc.x + (double)acc.y * acc.y
             + (double)acc.z * acc.z + (double)acc.w * acc.w;
        *((float4*)(g_res + (size_t)row * NDIM) + tid) = acc;
    }
    if (errSlot >= 0) {
        red[tid] = lerr; __syncthreads();
        for (int off = 128; off; off >>= 1) {
            if (tid < off) red[tid] += red[tid + off];
            __syncthreads();
        }
        if (tid == 0) atomicAdd(&g_err2[errSlot], red[0]);
    }
}

// ---------------- outputs ----------------
__global__ __launch_bounds__(256) void write_x(float* __restrict__ out) {
    __shared__ int sidx[CAP];
    __shared__ float sval[CAP];
    int row = blockIdx.x, tid = threadIdx.x;
    int cnt = g_cnt[row];
    if (tid < cnt) {
        sidx[tid] = g_idx[(size_t)row * CAP + tid];
        sval[tid] = g_val[(size_t)row * CAP + tid];
    }
    __syncthreads();
    if (tid < NC4) {
        unsigned long long acc2[2] = {0ull, 0ull};
        for (int s = 0; s < cnt; s++) {
            unsigned long long vd = pack_dup(sval[s]);
            float4 w = *((const float4*)(g_WT + (size_t)sidx[s] * NDIM) + tid);
            ffma2(acc2[0], vd, pack2(w.x, w.y));
            ffma2(acc2[1], vd, pack2(w.z, w.w));
        }
        float2 r0 = unpack2(acc2[0]), r1 = unpack2(acc2[1]);
        *((float4*)(out + (size_t)row * NDIM) + tid) = make_float4(r0.x, r0.y, r1.x, r1.y);
    }
}

__global__ __launch_bounds__(256) void copy_gamma(float* __restrict__ out) {
    size_t stride = (size_t)gridDim.x * blockDim.x;
    size_t n4 = (size_t)BDIM * MDIM / 4;
    const float4* src = (const float4*)g_Gd;
    float4* dst = (float4*)out;
    for (size_t e = blockIdx.x * (size_t)blockDim.x + threadIdx.x; e < n4; e += stride)
        dst[e] = src[e];
}

__global__ void write_err(float* __restrict__ out) {
    int t = threadIdx.x;
    if (t < IHTIT) {
        float rn = sqrtf((float)g_err2[t]);
        float yn = sqrtf((float)g_yn2);
        out[t] = __fdiv_rn(rn, yn);
    }
}

// ---------------- host ----------------
extern "C" void kernel_launch(void* const* d_in, const int* in_sizes, int n_in,
                              void* d_out, int out_size) {
    const float* Y  = (const float*)d_in[0];
    const float* W  = (const float*)d_in[1];
    const float* pm = (const float*)d_in[2];
    const int*   Kp = (const int*)d_in[3];
    float* out = (float*)d_out;
    (void)in_sizes; (void)n_in;

    zero_kernel<<<8, 256>>>(pm);
    colnorm_kernel<<<MDIM / 256, 256>>>(W);
    buildwn_kernel<<<1024, 256>>>(W);
    ynorm_kernel<<<512, 256>>>(Y, BDIM * NDIM);

    pm_persist<<<PMB, 256>>>();
    buildew_kernel<<<1024, 256>>>();

    dim3 gGemm(MDIM / 128, BDIM / 128);   // 16 x 32
    sgemm_seq<<<gGemm, 256>>>(Y, 0);            // U = Y @ (eta*Wn)
    select_spout<<<BDIM, 256>>>(Y, Kp, -1);     // Gamma_0 + residual_0

    for (int t = 1; t <= IHTIT; t++) {
        sgemm_seq<<<gGemm, 256>>>(Y, 1);            // U = Gd - eta*(res@Wn)
        select_spout<<<BDIM, 256>>>(Y, Kp, t - 1);  // Gamma_t + residual_t + err
    }

    long long GOFF = (long long)BDIM * NDIM;          // 3211264
    long long EOFF = GOFF + (long long)BDIM * MDIM;   // 11599872

    write_x<<<BDIM, 256>>>(out);
    if ((long long)out_size >= EOFF)
        copy_gamma<<<1024, 256>>>(out + GOFF);
    if ((long long)out_size >= EOFF + IHTIT)
        write_err<<<1, 64>>>(out + EOFF);
}